// round 3
// baseline (speedup 1.0000x reference)
#include <cuda_runtime.h>

// Problem: x [SEQ_LEN=4194304, E=8] fp32. Keep row iff expert 0 is in the
// row's top-2 (jax.lax.top_k ties break to the lowest index, i.e. expert 0),
// else zero the row. Predicate: count(x[j] > x[0], j=1..7) <= 1.
//
// One row (32 B) per thread: two LDG.128 at +0/+16. Lane addresses stride
// 32 B -> every 32 B sector hit exactly once per warp-load; full coalescing
// at sector granularity. No shuffles, no divergence; MLP_p1 = 2.
// HBM-bound: 256 MiB total traffic, target ~6.3 TB/s -> ~42 us.

__global__ void __launch_bounds__(256)
routing_e0_kernel(const float4* __restrict__ in,
                  float4* __restrict__ out,
                  int nrows)
{
    int row = blockIdx.x * blockDim.x + threadIdx.x;
    if (row >= nrows) return;

    float4 a = in[2 * row];       // x[0..3]
    float4 b = in[2 * row + 1];   // x[4..7]

    float x0 = a.x;
    int cnt = (a.y > x0) + (a.z > x0) + (a.w > x0)
            + (b.x > x0) + (b.y > x0) + (b.z > x0) + (b.w > x0);

    // Keep row iff at most 1 element beats x0 (expert 0 in top-2).
    float keep = (cnt <= 1) ? 1.0f : 0.0f;

    float4 ra, rb;
    ra.x = a.x * keep;  ra.y = a.y * keep;
    ra.z = a.z * keep;  ra.w = a.w * keep;
    rb.x = b.x * keep;  rb.y = b.y * keep;
    rb.z = b.z * keep;  rb.w = b.w * keep;

    out[2 * row]     = ra;
    out[2 * row + 1] = rb;
}

extern "C" void kernel_launch(void* const* d_in, const int* in_sizes, int n_in,
                              void* d_out, int out_size)
{
    const float4* in  = (const float4*)d_in[0];
    float4*       out = (float4*)d_out;

    int n_elems = in_sizes[0];     // SEQ_LEN * 8 floats
    int nrows = n_elems / 8;       // rows of 8 experts

    const int threads = 256;
    int blocks = (nrows + threads - 1) / threads;
    routing_e0_kernel<<<blocks, threads>>>(in, out, nrows);
}